// round 8
// baseline (speedup 1.0000x reference)
#include <cuda_runtime.h>
#include <cuda_fp16.h>
#include <math.h>
#include <stdint.h>

#define BN_EPS 1e-5f

// ---------------------------------------------------------------------------
// Global scratch: fp16 operands
// ---------------------------------------------------------------------------
__device__ __half g_w1h[128*2304];                 // k = r*256+ci
__device__ __half g_w2h[256*1152];                 // k = r*128+ci
__device__ __half g_xt [16u*4096*256];             // x^T  [b][p][ci]
__device__ __half g_y1 [16u*128*4096];             // y1   [b][c][p]
__device__ __half g_y1t[16u*4096*128];             // y1^T [b][p][ci]
__device__ __half g_y2 [16u*256*4096];             // y2   [b][c][p]
__device__ __half g_y2t[16u*4096*256];             // y2^T [b][p][c]
__device__ float  g_sc [16u*256*256];
__device__ __half g_at [16u*256*256];              // attn

// ---------------------------------------------------------------------------
__device__ __forceinline__ uint32_t smem_u32(const void* p) {
    uint32_t a;
    asm("{ .reg .u64 t; cvta.to.shared.u64 t, %1; cvt.u32.u64 %0, t; }" : "=r"(a) : "l"(p));
    return a;
}
__device__ __forceinline__ void ldsm_x4(uint32_t addr, uint32_t r[4]) {
    asm volatile("ldmatrix.sync.aligned.m8n8.x4.shared.b16 {%0,%1,%2,%3}, [%4];"
                 : "=r"(r[0]), "=r"(r[1]), "=r"(r[2]), "=r"(r[3]) : "r"(addr));
}
__device__ __forceinline__ void mma16816(float d[4], const uint32_t a[4],
                                         uint32_t b0, uint32_t b1) {
    asm volatile(
        "mma.sync.aligned.m16n8k16.row.col.f32.f16.f16.f32 "
        "{%0,%1,%2,%3}, {%4,%5,%6,%7}, {%8,%9}, {%0,%1,%2,%3};"
        : "+f"(d[0]), "+f"(d[1]), "+f"(d[2]), "+f"(d[3])
        : "r"(a[0]), "r"(a[1]), "r"(a[2]), "r"(a[3]), "r"(b0), "r"(b1));
}
__device__ __forceinline__ uint32_t sw128(uint32_t off) {
    return off ^ ((off >> 3) & 0x70);
}
__device__ __forceinline__ void cp16(uint32_t dst, const void* src, int sz) {
    asm volatile("cp.async.cg.shared.global [%0], [%1], 16, %2;"
                 :: "r"(dst), "l"(src), "r"(sz) : "memory");
}
__device__ __forceinline__ void cp_commit() {
    asm volatile("cp.async.commit_group;" ::: "memory");
}

// ---------------------------------------------------------------------------
// fp16 GEMM on HMMA. CTA tile 128x128, warps 2(M) x 4(N), warp tile 64x32.
// 3-stage cp.async pipeline (stage 32KB: A 16KB @0, B 16KB @16384).
// MODE 0: conv (BN+SiLU -> fp16 out), B = shifted transposed image planes
// MODE 1: scores (x 1/16 -> fp32)
// MODE 2: out (+ residual -> fp32)
// ---------------------------------------------------------------------------
template <int MODE, int CI>
__global__ __launch_bounds__(256, 2)
void gemm_fp16(const __half* __restrict__ Ag, int lda,
               const __half* __restrict__ Bg, int K,
               const float* __restrict__ p0, const float* __restrict__ p1,
               const float* __restrict__ p2, const float* __restrict__ p3,
               const float* __restrict__ resid,
               __half* __restrict__ outh, float* __restrict__ outf)
{
    extern __shared__ char sm[];
    const int t    = threadIdx.x;
    const int lane = t & 31, warp = t >> 5;
    const int wm   = (warp >> 2) * 64;   // 2 M groups of 64
    const int wn   = (warp & 3) * 32;    // 4 N groups of 32
    const int b = blockIdx.z, bm = blockIdx.y, bn = blockIdx.x;
    const uint32_t sb = smem_u32(sm);

    const __half *Ab, *Bb;
    if (MODE == 0) {
        Ab = Ag; Bb = Bg + (size_t)b * 4096 * CI;
    } else if (MODE == 1) {
        size_t o = (size_t)b * 256 * 4096;
        Ab = Ag + o; Bb = Bg + o;
    } else {
        Ab = Ag + (size_t)b * 256 * 256; Bb = Bg + (size_t)b * 4096 * 256;
    }
    const int ldb = (MODE == 1) ? 4096 : 256;

    float acc[4][4][4];
#pragma unroll
    for (int i = 0; i < 4; ++i)
#pragma unroll
        for (int j = 0; j < 4; ++j)
#pragma unroll
            for (int q = 0; q < 4; ++q) acc[i][j][q] = 0.f;

    // Hoisted ldsm address components
    const int a_row = (lane & 7) + ((lane >> 3) & 1) * 8;
    const int a_chk = lane >> 4;            // 0/1 -> +16B
    const int b_row = (lane & 7) + ((lane >> 4) & 1) * 8;
    const int b_chk = (lane >> 3) & 1;
    uint32_t a_base[4], a_xor[4];
#pragma unroll
    for (int mt = 0; mt < 4; ++mt) {
        const int row = wm + mt * 16 + a_row;
        a_base[mt] = row * 128;
        a_xor[mt]  = ((row & 7) << 4) ;
    }
    uint32_t b_base[2], b_xor[2];
#pragma unroll
    for (int ng = 0; ng < 2; ++ng) {
        const int row = wn + ng * 16 + b_row;
        b_base[ng] = row * 128;
        b_xor[ng]  = ((row & 7) << 4);
    }

    auto prefetch = [&](int kt, int stage) {
        const uint32_t base = sb + stage * 32768;
        // ---- A: 128 rows x 128B ----
#pragma unroll
        for (int i = 0; i < 4; ++i) {
            const int task = t + i * 256, m = task >> 3, g = task & 7;
            const size_t so = (size_t)(bm * 128 + m) * lda + kt * 64 + g * 8;
            cp16(base + sw128(m * 128 + g * 16), Ab + so, 16);
        }
        // ---- B: 128 rows x 128B ----
        if (MODE == 0) {
            constexpr int CPR = CI / 64;
            const int r  = kt / CPR;
            const int ci0 = (kt - r * CPR) * 64;
            const int dh = r / 3 - 1, dw = (r - (r / 3) * 3) - 1;
#pragma unroll
            for (int i = 0; i < 4; ++i) {
                const int task = t + i * 256, m = task >> 3, g = task & 7;
                const int p = bn * 128 + m, h = p >> 6, w = p & 63;
                const int hh = h + dh, ww = w + dw;
                const bool ok = ((unsigned)hh < 64u) && ((unsigned)ww < 64u);
                const size_t so = ok ? (size_t)((hh << 6) + ww) * CI + ci0 + g * 8 : 0;
                cp16(base + 16384 + sw128(m * 128 + g * 16), Bb + so, ok ? 16 : 0);
            }
        } else {
#pragma unroll
            for (int i = 0; i < 4; ++i) {
                const int task = t + i * 256, m = task >> 3, g = task & 7;
                const size_t so = (size_t)(bn * 128 + m) * ldb + kt * 64 + g * 8;
                cp16(base + 16384 + sw128(m * 128 + g * 16), Bb + so, 16);
            }
        }
    };

    const int nch = K / 64;
    prefetch(0, 0); cp_commit();
    prefetch(1, 1); cp_commit();

    int scur = 0;
    for (int kt = 0; kt < nch; ++kt) {
        if (kt + 1 < nch) { asm volatile("cp.async.wait_group 1;" ::: "memory"); }
        else              { asm volatile("cp.async.wait_group 0;" ::: "memory"); }
        __syncthreads();
        if (kt + 2 < nch) {
            int spf = scur + 2; if (spf >= 3) spf -= 3;
            prefetch(kt + 2, spf);
            cp_commit();
        }

        const uint32_t abase = sb + scur * 32768;
        const uint32_t bbase = abase + 16384;
#pragma unroll
        for (int ks = 0; ks < 4; ++ks) {
            const uint32_t acol = (uint32_t)((ks * 2 + a_chk) * 16);
            const uint32_t bcol = (uint32_t)((ks * 2 + b_chk) * 16);
            uint32_t ah[4][4];
#pragma unroll
            for (int mt = 0; mt < 4; ++mt)
                ldsm_x4(abase + a_base[mt] + (acol ^ a_xor[mt]), ah[mt]);
#pragma unroll
            for (int ng = 0; ng < 2; ++ng) {
                uint32_t bh[4];
                ldsm_x4(bbase + b_base[ng] + (bcol ^ b_xor[ng]), bh);
#pragma unroll
                for (int mt = 0; mt < 4; ++mt) {
                    mma16816(acc[mt][2 * ng],     ah[mt], bh[0], bh[1]);
                    mma16816(acc[mt][2 * ng + 1], ah[mt], bh[2], bh[3]);
                }
            }
        }
        ++scur; if (scur == 3) scur = 0;
    }

    // ----------------------- epilogue -----------------------
    const int r0 = bm * 128 + wm + (lane >> 2);
    const int c0 = bn * 128 + wn + (lane & 3) * 2;

    if (MODE == 0) {
        const int CO = gridDim.y * 128;
#pragma unroll
        for (int mt = 0; mt < 4; ++mt) {
#pragma unroll
            for (int half = 0; half < 2; ++half) {
                const int co = r0 + mt * 16 + half * 8;
                const float scl = p0[co] * rsqrtf(p3[co] + BN_EPS);
                const float shf = p1[co] - p2[co] * scl;
                __half* dst = outh + ((size_t)(b * CO + co)) * 4096;
#pragma unroll
                for (int nt = 0; nt < 4; ++nt) {
                    float y0 = acc[mt][nt][2 * half]     * scl + shf;
                    float y1 = acc[mt][nt][2 * half + 1] * scl + shf;
                    y0 = y0 / (1.f + expf(-y0));
                    y1 = y1 / (1.f + expf(-y1));
                    *reinterpret_cast<__half2*>(dst + c0 + nt * 8) =
                        __floats2half2_rn(y0, y1);
                }
            }
        }
    } else if (MODE == 1) {
#pragma unroll
        for (int mt = 0; mt < 4; ++mt) {
#pragma unroll
            for (int half = 0; half < 2; ++half) {
                const int c = r0 + mt * 16 + half * 8;
                float* dst = outf + ((size_t)b * 256 + c) * 256;
#pragma unroll
                for (int nt = 0; nt < 4; ++nt) {
                    *reinterpret_cast<float2*>(dst + c0 + nt * 8) =
                        make_float2(acc[mt][nt][2 * half] * 0.0625f,
                                    acc[mt][nt][2 * half + 1] * 0.0625f);
                }
            }
        }
    } else {
#pragma unroll
        for (int mt = 0; mt < 4; ++mt) {
#pragma unroll
            for (int half = 0; half < 2; ++half) {
                const int c = r0 + mt * 16 + half * 8;
                const size_t base2 = ((size_t)(b * 256 + c)) * 4096;
#pragma unroll
                for (int nt = 0; nt < 4; ++nt) {
                    float2 rx = *reinterpret_cast<const float2*>(resid + base2 + c0 + nt * 8);
                    *reinterpret_cast<float2*>(outf + base2 + c0 + nt * 8) =
                        make_float2(acc[mt][nt][2 * half] + rx.x,
                                    acc[mt][nt][2 * half + 1] + rx.y);
                }
            }
        }
    }
}

// ---------------------------------------------------------------------------
// Helpers
// ---------------------------------------------------------------------------
__global__ __launch_bounds__(256) void w_reorder(const float* __restrict__ w,
                                                 __half* __restrict__ wh,
                                                 int CO, int CIc) {
    int idx = blockIdx.x * 256 + threadIdx.x;
    int total = CO * CIc * 9;
    if (idx >= total) return;
    int K  = CIc * 9;
    int co = idx / K;
    int rem = idx - co * K;
    int r  = rem / CIc;
    int ci = rem - r * CIc;
    wh[idx] = __float2half_rn(w[(size_t)co * K + ci * 9 + r]);
}

__global__ __launch_bounds__(256) void x_tr(const float* __restrict__ x,
                                            __half* __restrict__ xt) {
    __shared__ uint16_t tile[64][65];
    const int b = blockIdx.z, p0 = blockIdx.x * 32, c0 = blockIdx.y * 64;
    const float* s = x + (size_t)b * 256 * 4096;
    const int t = threadIdx.x;
#pragma unroll
    for (int i = 0; i < 8; ++i) {
        int task = t + i * 256;
        int c = task >> 5, p = task & 31;
        tile[c][p] = __half_as_ushort(__float2half_rn(s[(size_t)(c0 + c) * 4096 + p0 + p]));
    }
    __syncthreads();
#pragma unroll
    for (int i = 0; i < 4; ++i) {
        int task = t + i * 256;
        int p = task >> 5, c2 = task & 31;
        uint32_t v = (uint32_t)tile[2 * c2][p] | ((uint32_t)tile[2 * c2 + 1][p] << 16);
        *reinterpret_cast<uint32_t*>(xt + (size_t)(b * 4096 + p0 + p) * 256 + c0 + 2 * c2) = v;
    }
}

__global__ __launch_bounds__(256) void h_tr(const __half* __restrict__ src,
                                            __half* __restrict__ dst, int C) {
    __shared__ uint16_t tile[64][65];
    const int b = blockIdx.z, p0 = blockIdx.x * 64, c0 = blockIdx.y * 64;
    const __half* s = src + (size_t)b * C * 4096;
    __half*       d = dst + (size_t)b * 4096 * C;
    const int t = threadIdx.x;
#pragma unroll
    for (int i = 0; i < 8; ++i) {
        int task = t + i * 256;
        int c = task >> 5, p2 = task & 31;
        uint32_t v = *reinterpret_cast<const uint32_t*>(s + (size_t)(c0 + c) * 4096 + p0 + 2 * p2);
        tile[c][2 * p2]     = (uint16_t)v;
        tile[c][2 * p2 + 1] = (uint16_t)(v >> 16);
    }
    __syncthreads();
#pragma unroll
    for (int i = 0; i < 8; ++i) {
        int task = t + i * 256;
        int p = task >> 5, c2 = task & 31;
        uint32_t v = (uint32_t)tile[2 * c2][p] | ((uint32_t)tile[2 * c2 + 1][p] << 16);
        *reinterpret_cast<uint32_t*>(d + (size_t)(p0 + p) * C + c0 + 2 * c2) = v;
    }
}

__global__ __launch_bounds__(256) void softmax_h(const float* __restrict__ s,
                                                 __half* __restrict__ a) {
    __shared__ float redmax[8];
    __shared__ float redsum[8];
    const float* r = s + (size_t)blockIdx.x * 256;
    const int t = threadIdx.x;

    float v = r[t];
    float m = v;
#pragma unroll
    for (int o = 16; o; o >>= 1) m = fmaxf(m, __shfl_xor_sync(0xffffffffu, m, o));
    if ((t & 31) == 0) redmax[t >> 5] = m;
    __syncthreads();
    m = redmax[0];
#pragma unroll
    for (int i = 1; i < 8; ++i) m = fmaxf(m, redmax[i]);

    float e = expf(v - m);
    float sum = e;
#pragma unroll
    for (int o = 16; o; o >>= 1) sum += __shfl_xor_sync(0xffffffffu, sum, o);
    if ((t & 31) == 0) redsum[t >> 5] = sum;
    __syncthreads();
    sum = 0.f;
#pragma unroll
    for (int i = 0; i < 8; ++i) sum += redsum[i];

    a[(size_t)blockIdx.x * 256 + t] = __float2half_rn(e / sum);
}

// ---------------------------------------------------------------------------
extern "C" void kernel_launch(void* const* d_in, const int* in_sizes, int n_in,
                              void* d_out, int out_size)
{
    const float* x  = (const float*)d_in[0];
    const float* w1 = (const float*)d_in[1];
    const float* g1 = (const float*)d_in[2];
    const float* b1 = (const float*)d_in[3];
    const float* m1 = (const float*)d_in[4];
    const float* v1 = (const float*)d_in[5];
    const float* w2 = (const float*)d_in[6];
    const float* g2 = (const float*)d_in[7];
    const float* b2 = (const float*)d_in[8];
    const float* m2 = (const float*)d_in[9];
    const float* v2 = (const float*)d_in[10];
    float* out = (float*)d_out;

    __half *w1h, *w2h, *xt, *y1, *y1t, *y2, *y2t, *at;
    float* sc;
    cudaGetSymbolAddress((void**)&w1h, g_w1h);
    cudaGetSymbolAddress((void**)&w2h, g_w2h);
    cudaGetSymbolAddress((void**)&xt,  g_xt);
    cudaGetSymbolAddress((void**)&y1,  g_y1);
    cudaGetSymbolAddress((void**)&y1t, g_y1t);
    cudaGetSymbolAddress((void**)&y2,  g_y2);
    cudaGetSymbolAddress((void**)&y2t, g_y2t);
    cudaGetSymbolAddress((void**)&sc,  g_sc);
    cudaGetSymbolAddress((void**)&at,  g_at);

    const int SMB = 98304;   // 3 stages x 32KB
    cudaFuncSetAttribute(gemm_fp16<0, 256>, cudaFuncAttributeMaxDynamicSharedMemorySize, SMB);
    cudaFuncSetAttribute(gemm_fp16<0, 128>, cudaFuncAttributeMaxDynamicSharedMemorySize, SMB);
    cudaFuncSetAttribute(gemm_fp16<1, 0>,   cudaFuncAttributeMaxDynamicSharedMemorySize, SMB);
    cudaFuncSetAttribute(gemm_fp16<2, 0>,   cudaFuncAttributeMaxDynamicSharedMemorySize, SMB);

    // ---- operand prep ----
    w_reorder<<<(128 * 2304 + 255) / 256, 256>>>(w1, w1h, 128, 256);
    w_reorder<<<(256 * 1152 + 255) / 256, 256>>>(w2, w2h, 256, 128);
    x_tr<<<dim3(128, 4, 16), 256>>>(x, xt);

    // conv1: [B,256,64,64] -> y1 [B,128,64,64]
    gemm_fp16<0, 256><<<dim3(32, 1, 16), 256, SMB>>>(
        w1h, 2304, xt, 2304, g1, b1, m1, v1, nullptr, y1, nullptr);
    h_tr<<<dim3(64, 2, 16), 256>>>(y1, y1t, 128);

    // conv2: -> y2 [B,256,64,64]
    gemm_fp16<0, 128><<<dim3(32, 2, 16), 256, SMB>>>(
        w2h, 1152, y1t, 1152, g2, b2, m2, v2, nullptr, y2, nullptr);
    h_tr<<<dim3(64, 4, 16), 256>>>(y2, y2t, 256);

    // scores = (q q^T)/16
    gemm_fp16<1, 0><<<dim3(2, 2, 16), 256, SMB>>>(
        y2, 4096, y2, 4096, nullptr, nullptr, nullptr, nullptr, nullptr, nullptr, sc);
    softmax_h<<<4096, 256>>>(sc, at);

    // out = attn * q + x
    gemm_fp16<2, 0><<<dim3(32, 2, 16), 256, SMB>>>(
        at, 256, y2t, 256, nullptr, nullptr, nullptr, nullptr, x, nullptr, out);
}

// round 10
// speedup vs baseline: 1.0295x; 1.0295x over previous
#include <cuda_runtime.h>
#include <cuda_fp16.h>
#include <math.h>
#include <stdint.h>

#define BN_EPS 1e-5f

// ---------------------------------------------------------------------------
// Global scratch
// ---------------------------------------------------------------------------
__device__ __half g_w1h[128*2304];                 // k = r*256+ci
__device__ __half g_w2h[256*1152];                 // k = r*128+ci
__device__ __half g_xt [16u*4096*256];             // x^T  [b][p][ci]
__device__ __half g_y1 [16u*128*4096];             // y1   [b][c][p]
__device__ __half g_y1t[16u*4096*128];             // y1^T [b][p][ci]
__device__ __half g_y2 [16u*256*4096];             // y2   [b][c][p]
__device__ __half g_y2t[16u*4096*256];             // y2^T [b][p][c]
__device__ float  g_scp[64u*256*256];              // score partials [b*4+ks][c][d]
__device__ __half g_at [16u*256*256];              // attn

// ---------------------------------------------------------------------------
__device__ __forceinline__ uint32_t smem_u32(const void* p) {
    uint32_t a;
    asm("{ .reg .u64 t; cvta.to.shared.u64 t, %1; cvt.u32.u64 %0, t; }" : "=r"(a) : "l"(p));
    return a;
}
__device__ __forceinline__ void ldsm_x4(uint32_t addr, uint32_t r[4]) {
    asm volatile("ldmatrix.sync.aligned.m8n8.x4.shared.b16 {%0,%1,%2,%3}, [%4];"
                 : "=r"(r[0]), "=r"(r[1]), "=r"(r[2]), "=r"(r[3]) : "r"(addr));
}
__device__ __forceinline__ void mma16816(float d[4], const uint32_t a[4],
                                         uint32_t b0, uint32_t b1) {
    asm volatile(
        "mma.sync.aligned.m16n8k16.row.col.f32.f16.f16.f32 "
        "{%0,%1,%2,%3}, {%4,%5,%6,%7}, {%8,%9}, {%0,%1,%2,%3};"
        : "+f"(d[0]), "+f"(d[1]), "+f"(d[2]), "+f"(d[3])
        : "r"(a[0]), "r"(a[1]), "r"(a[2]), "r"(a[3]), "r"(b0), "r"(b1));
}
__device__ __forceinline__ uint32_t sw128(uint32_t off) {
    return off ^ ((off >> 3) & 0x70);
}
__device__ __forceinline__ void cp16(uint32_t dst, const void* src, int sz) {
    asm volatile("cp.async.cg.shared.global [%0], [%1], 16, %2;"
                 :: "r"(dst), "l"(src), "r"(sz) : "memory");
}
__device__ __forceinline__ void cp_commit() {
    asm volatile("cp.async.commit_group;" ::: "memory");
}

// ---------------------------------------------------------------------------
// fp16 GEMM on HMMA. CTA tile 128(M)x64(N), warps 4(M)x2(N), warp 32x32.
// Double-buffered cp.async, ONE sync per chunk. Stage 24KB: A 16KB, B 8KB.
// MODE 0: conv (BN+SiLU -> fp16), B = shifted transposed image planes
// MODE 1: scores partial (x 1/16 -> fp32 partial; z = b*4+kslice, K=1024)
// MODE 2: out (+ residual -> fp32)
// ---------------------------------------------------------------------------
template <int MODE, int CI>
__global__ __launch_bounds__(256, 2)
void gemm_fp16(const __half* __restrict__ Ag, int lda,
               const __half* __restrict__ Bg, int K,
               const float* __restrict__ p0, const float* __restrict__ p1,
               const float* __restrict__ p2, const float* __restrict__ p3,
               const float* __restrict__ resid,
               __half* __restrict__ outh, float* __restrict__ outf)
{
    extern __shared__ char sm[];
    const int t    = threadIdx.x;
    const int lane = t & 31, warp = t >> 5;
    const int wm   = (warp >> 1) * 32;   // 4 M groups of 32
    const int wn   = (warp & 1) * 32;    // 2 N groups of 32
    const int bm = blockIdx.y, bn = blockIdx.x;
    const int b  = (MODE == 1) ? (blockIdx.z >> 2) : blockIdx.z;
    const uint32_t sb = smem_u32(sm);

    const __half *Ab, *Bb;
    if (MODE == 0) {
        Ab = Ag; Bb = Bg + (size_t)b * 4096 * CI;
    } else if (MODE == 1) {
        const int ks = blockIdx.z & 3;
        size_t o = (size_t)b * 256 * 4096 + (size_t)ks * 1024;
        Ab = Ag + o; Bb = Bg + o;
    } else {
        Ab = Ag + (size_t)b * 256 * 256; Bb = Bg + (size_t)b * 4096 * 256;
    }
    const int ldb = (MODE == 1) ? 4096 : 256;

    float acc[2][4][4];
#pragma unroll
    for (int i = 0; i < 2; ++i)
#pragma unroll
        for (int j = 0; j < 4; ++j)
#pragma unroll
            for (int q = 0; q < 4; ++q) acc[i][j][q] = 0.f;

    // Hoisted prefetch source offsets (element offsets, 32-bit)
    const int pg = t & 7;
    uint32_t a_src[4];
#pragma unroll
    for (int i = 0; i < 4; ++i) {
        const int m = (t + i * 256) >> 3;
        a_src[i] = (uint32_t)((bm * 128 + m) * lda + pg * 8);
    }
    uint32_t b_src[2];
    int b_h[2], b_w[2];
#pragma unroll
    for (int i = 0; i < 2; ++i) {
        const int m = (t + i * 256) >> 3;
        if (MODE == 0) {
            const int p = bn * 64 + m;
            b_h[i] = p >> 6; b_w[i] = p & 63;
            b_src[i] = (uint32_t)(p * CI + pg * 8);
        } else {
            b_src[i] = (uint32_t)((bn * 64 + m) * ldb + pg * 8);
        }
    }

    // Hoisted ldsm addressing
    const int a_row = (lane & 7) + ((lane >> 3) & 1) * 8;
    const int a_chk = lane >> 4;
    const int b_row = (lane & 7) + ((lane >> 4) & 1) * 8;
    const int b_chk = (lane >> 3) & 1;
    uint32_t a_base[2], a_xor[2];
#pragma unroll
    for (int mt = 0; mt < 2; ++mt) {
        const int row = wm + mt * 16 + a_row;
        a_base[mt] = row * 128; a_xor[mt] = (row & 7) << 4;
    }
    uint32_t b_base[2], b_xor[2];
#pragma unroll
    for (int ng = 0; ng < 2; ++ng) {
        const int row = wn + ng * 16 + b_row;
        b_base[ng] = row * 128; b_xor[ng] = (row & 7) << 4;
    }

    auto prefetch = [&](int kt, int stage) {
        const uint32_t base = sb + stage * 24576;
#pragma unroll
        for (int i = 0; i < 4; ++i) {
            const int m = (t + i * 256) >> 3;
            cp16(base + sw128(m * 128 + pg * 16), Ab + a_src[i] + kt * 64, 16);
        }
        if (MODE == 0) {
            constexpr int CPR = CI / 64;
            const int r  = kt / CPR;
            const int ci0 = (kt - r * CPR) * 64;
            const int dh = r / 3 - 1, dw = (r - (r / 3) * 3) - 1;
            const int delta = (dh * 64 + dw) * CI + ci0;
#pragma unroll
            for (int i = 0; i < 2; ++i) {
                const int m = (t + i * 256) >> 3;
                const int hh = b_h[i] + dh, ww = b_w[i] + dw;
                const bool ok = ((unsigned)hh < 64u) && ((unsigned)ww < 64u);
                cp16(base + 16384 + sw128(m * 128 + pg * 16),
                     Bb + (ok ? (b_src[i] + delta) : 0u), ok ? 16 : 0);
            }
        } else {
#pragma unroll
            for (int i = 0; i < 2; ++i) {
                const int m = (t + i * 256) >> 3;
                cp16(base + 16384 + sw128(m * 128 + pg * 16), Bb + b_src[i] + kt * 64, 16);
            }
        }
    };

    const int nch = K / 64;
    prefetch(0, 0);
    cp_commit();

    for (int kt = 0; kt < nch; ++kt) {
        const int stage = kt & 1;
        asm volatile("cp.async.wait_group 0;" ::: "memory");
        __syncthreads();
        if (kt + 1 < nch) {            // safe: barrier above proves stage^1 reads done
            prefetch(kt + 1, stage ^ 1);
            cp_commit();
        }

        const uint32_t abase = sb + stage * 24576;
        const uint32_t bbase = abase + 16384;
#pragma unroll
        for (int ks = 0; ks < 4; ++ks) {
            const uint32_t acol = (uint32_t)((ks * 2 + a_chk) * 16);
            const uint32_t bcol = (uint32_t)((ks * 2 + b_chk) * 16);
            uint32_t ah[2][4];
#pragma unroll
            for (int mt = 0; mt < 2; ++mt)
                ldsm_x4(abase + a_base[mt] + (acol ^ a_xor[mt]), ah[mt]);
#pragma unroll
            for (int ng = 0; ng < 2; ++ng) {
                uint32_t bh[4];
                ldsm_x4(bbase + b_base[ng] + (bcol ^ b_xor[ng]), bh);
#pragma unroll
                for (int mt = 0; mt < 2; ++mt) {
                    mma16816(acc[mt][2 * ng],     ah[mt], bh[0], bh[1]);
                    mma16816(acc[mt][2 * ng + 1], ah[mt], bh[2], bh[3]);
                }
            }
        }
    }

    // ----------------------- epilogue -----------------------
    const int r0 = bm * 128 + wm + (lane >> 2);
    const int c0 = bn * 64 + wn + (lane & 3) * 2;

    if (MODE == 0) {
        const int CO = gridDim.y * 128;
#pragma unroll
        for (int mt = 0; mt < 2; ++mt) {
#pragma unroll
            for (int half = 0; half < 2; ++half) {
                const int co = r0 + mt * 16 + half * 8;
                const float scl = p0[co] * rsqrtf(p3[co] + BN_EPS);
                const float shf = p1[co] - p2[co] * scl;
                __half* dst = outh + ((size_t)(b * CO + co)) * 4096;
#pragma unroll
                for (int nt = 0; nt < 4; ++nt) {
                    float y0 = acc[mt][nt][2 * half]     * scl + shf;
                    float y1 = acc[mt][nt][2 * half + 1] * scl + shf;
                    y0 = y0 / (1.f + expf(-y0));
                    y1 = y1 / (1.f + expf(-y1));
                    *reinterpret_cast<__half2*>(dst + c0 + nt * 8) =
                        __floats2half2_rn(y0, y1);
                }
            }
        }
    } else if (MODE == 1) {
        float* obase = outf + (size_t)blockIdx.z * 256 * 256;
#pragma unroll
        for (int mt = 0; mt < 2; ++mt) {
#pragma unroll
            for (int half = 0; half < 2; ++half) {
                float* dst = obase + (size_t)(r0 + mt * 16 + half * 8) * 256;
#pragma unroll
                for (int nt = 0; nt < 4; ++nt) {
                    *reinterpret_cast<float2*>(dst + c0 + nt * 8) =
                        make_float2(acc[mt][nt][2 * half] * 0.0625f,
                                    acc[mt][nt][2 * half + 1] * 0.0625f);
                }
            }
        }
    } else {
#pragma unroll
        for (int mt = 0; mt < 2; ++mt) {
#pragma unroll
            for (int half = 0; half < 2; ++half) {
                const int c = r0 + mt * 16 + half * 8;
                const size_t base2 = ((size_t)(b * 256 + c)) * 4096;
#pragma unroll
                for (int nt = 0; nt < 4; ++nt) {
                    float2 rx = *reinterpret_cast<const float2*>(resid + base2 + c0 + nt * 8);
                    *reinterpret_cast<float2*>(outf + base2 + c0 + nt * 8) =
                        make_float2(acc[mt][nt][2 * half] + rx.x,
                                    acc[mt][nt][2 * half + 1] + rx.y);
                }
            }
        }
    }
}

// ---------------------------------------------------------------------------
// Helpers
// ---------------------------------------------------------------------------
__global__ __launch_bounds__(256) void w_reorder(const float* __restrict__ w,
                                                 __half* __restrict__ wh,
                                                 int CO, int CIc) {
    int idx = blockIdx.x * 256 + threadIdx.x;
    int total = CO * CIc * 9;
    if (idx >= total) return;
    int K  = CIc * 9;
    int co = idx / K;
    int rem = idx - co * K;
    int r  = rem / CIc;
    int ci = rem - r * CIc;
    wh[idx] = __float2half_rn(w[(size_t)co * K + ci * 9 + r]);
}

__global__ __launch_bounds__(256) void x_tr(const float* __restrict__ x,
                                            __half* __restrict__ xt) {
    __shared__ uint16_t tile[64][65];
    const int b = blockIdx.z, p0 = blockIdx.x * 32, c0 = blockIdx.y * 64;
    const float* s = x + (size_t)b * 256 * 4096;
    const int t = threadIdx.x;
#pragma unroll
    for (int i = 0; i < 8; ++i) {
        int task = t + i * 256;
        int c = task >> 5, p = task & 31;
        tile[c][p] = __half_as_ushort(__float2half_rn(s[(size_t)(c0 + c) * 4096 + p0 + p]));
    }
    __syncthreads();
#pragma unroll
    for (int i = 0; i < 4; ++i) {
        int task = t + i * 256;
        int p = task >> 5, c2 = task & 31;
        uint32_t v = (uint32_t)tile[2 * c2][p] | ((uint32_t)tile[2 * c2 + 1][p] << 16);
        *reinterpret_cast<uint32_t*>(xt + (size_t)(b * 4096 + p0 + p) * 256 + c0 + 2 * c2) = v;
    }
}

__global__ __launch_bounds__(256) void h_tr(const __half* __restrict__ src,
                                            __half* __restrict__ dst, int C) {
    __shared__ uint16_t tile[64][65];
    const int b = blockIdx.z, p0 = blockIdx.x * 64, c0 = blockIdx.y * 64;
    const __half* s = src + (size_t)b * C * 4096;
    __half*       d = dst + (size_t)b * 4096 * C;
    const int t = threadIdx.x;
#pragma unroll
    for (int i = 0; i < 8; ++i) {
        int task = t + i * 256;
        int c = task >> 5, p2 = task & 31;
        uint32_t v = *reinterpret_cast<const uint32_t*>(s + (size_t)(c0 + c) * 4096 + p0 + 2 * p2);
        tile[c][2 * p2]     = (uint16_t)v;
        tile[c][2 * p2 + 1] = (uint16_t)(v >> 16);
    }
    __syncthreads();
#pragma unroll
    for (int i = 0; i < 8; ++i) {
        int task = t + i * 256;
        int p = task >> 5, c2 = task & 31;
        uint32_t v = (uint32_t)tile[2 * c2][p] | ((uint32_t)tile[2 * c2 + 1][p] << 16);
        *reinterpret_cast<uint32_t*>(d + (size_t)(p0 + p) * C + c0 + 2 * c2) = v;
    }
}

// softmax over 256, summing 4 K-slice partials. blockIdx.x = b*256 + c.
__global__ __launch_bounds__(256) void softmax_h(const float* __restrict__ sp,
                                                 __half* __restrict__ a) {
    __shared__ float redmax[8];
    __shared__ float redsum[8];
    const int brow = blockIdx.x;
    const int b = brow >> 8, c = brow & 255;
    const int t = threadIdx.x;
    const size_t rbase = ((size_t)(b * 4) * 256 + c) * 256 + t;

    float v = sp[rbase] + sp[rbase + 65536] + sp[rbase + 131072] + sp[rbase + 196608];

    float m = v;
#pragma unroll
    for (int o = 16; o; o >>= 1) m = fmaxf(m, __shfl_xor_sync(0xffffffffu, m, o));
    if ((t & 31) == 0) redmax[t >> 5] = m;
    __syncthreads();
    m = redmax[0];
#pragma unroll
    for (int i = 1; i < 8; ++i) m = fmaxf(m, redmax[i]);

    float e = expf(v - m);
    float sum = e;
#pragma unroll
    for (int o = 16; o; o >>= 1) sum += __shfl_xor_sync(0xffffffffu, sum, o);
    if ((t & 31) == 0) redsum[t >> 5] = sum;
    __syncthreads();
    sum = 0.f;
#pragma unroll
    for (int i = 0; i < 8; ++i) sum += redsum[i];

    a[(size_t)brow * 256 + t] = __float2half_rn(e / sum);
}

// ---------------------------------------------------------------------------
extern "C" void kernel_launch(void* const* d_in, const int* in_sizes, int n_in,
                              void* d_out, int out_size)
{
    const float* x  = (const float*)d_in[0];
    const float* w1 = (const float*)d_in[1];
    const float* g1 = (const float*)d_in[2];
    const float* b1 = (const float*)d_in[3];
    const float* m1 = (const float*)d_in[4];
    const float* v1 = (const float*)d_in[5];
    const float* w2 = (const float*)d_in[6];
    const float* g2 = (const float*)d_in[7];
    const float* b2 = (const float*)d_in[8];
    const float* m2 = (const float*)d_in[9];
    const float* v2 = (const float*)d_in[10];
    float* out = (float*)d_out;

    __half *w1h, *w2h, *xt, *y1, *y1t, *y2, *y2t, *at;
    float* scp;
    cudaGetSymbolAddress((void**)&w1h, g_w1h);
    cudaGetSymbolAddress((void**)&w2h, g_w2h);
    cudaGetSymbolAddress((void**)&xt,  g_xt);
    cudaGetSymbolAddress((void**)&y1,  g_y1);
    cudaGetSymbolAddress((void**)&y1t, g_y1t);
    cudaGetSymbolAddress((void**)&y2,  g_y2);
    cudaGetSymbolAddress((void**)&y2t, g_y2t);
    cudaGetSymbolAddress((void**)&scp, g_scp);
    cudaGetSymbolAddress((void**)&at,  g_at);

    const int SMB = 49152;   // 2 stages x 24KB
    cudaFuncSetAttribute(gemm_fp16<0, 256>, cudaFuncAttributeMaxDynamicSharedMemorySize, SMB);
    cudaFuncSetAttribute(gemm_fp16<0, 128>, cudaFuncAttributeMaxDynamicSharedMemorySize, SMB);
    cudaFuncSetAttribute(gemm_fp16<1, 0>,   cudaFuncAttributeMaxDynamicSharedMemorySize, SMB);
    cudaFuncSetAttribute(gemm_fp16<2, 0>,   cudaFuncAttributeMaxDynamicSharedMemorySize, SMB);

    // ---- operand prep ----
    w_reorder<<<(128 * 2304 + 255) / 256, 256>>>(w1, w1h, 128, 256);
    w_reorder<<<(256 * 1152 + 255) / 256, 256>>>(w2, w2h, 256, 128);
    x_tr<<<dim3(128, 4, 16), 256>>>(x, xt);

    // conv1: [B,256,64,64] -> y1 [B,128,64,64]
    gemm_fp16<0, 256><<<dim3(64, 1, 16), 256, SMB>>>(
        w1h, 2304, xt, 2304, g1, b1, m1, v1, nullptr, y1, nullptr);
    h_tr<<<dim3(64, 2, 16), 256>>>(y1, y1t, 128);

    // conv2: -> y2 [B,256,64,64]
    gemm_fp16<0, 128><<<dim3(64, 2, 16), 256, SMB>>>(
        w2h, 1152, y1t, 1152, g2, b2, m2, v2, nullptr, y2, nullptr);
    h_tr<<<dim3(64, 4, 16), 256>>>(y2, y2t, 256);

    // scores partials: z = b*4+ks, each slice K=1024 (FIX: was 4096)
    gemm_fp16<1, 0><<<dim3(4, 2, 64), 256, SMB>>>(
        y2, 4096, y2, 1024, nullptr, nullptr, nullptr, nullptr, nullptr, nullptr, scp);
    softmax_h<<<4096, 256>>>(scp, at);

    // out = attn * q + x
    gemm_fp16<2, 0><<<dim3(64, 2, 16), 256, SMB>>>(
        at, 256, y2t, 256, nullptr, nullptr, nullptr, nullptr, x, nullptr, out);
}